// round 1
// baseline (speedup 1.0000x reference)
#include <cuda_runtime.h>

#define POOL 7
#define CELLS (POOL * POOL)

__global__ __launch_bounds__(256) void pyramid_roialign_kernel(
    const float* __restrict__ boxes,   // (B, N, 4)  y1,x1,y2,x2
    const float* __restrict__ meta,    // (B, 14)
    const float* __restrict__ f2,      // (B, 256, 256, C)
    const float* __restrict__ f3,      // (B, 128, 128, C)
    const float* __restrict__ f4,      // (B,  64,  64, C)
    const float* __restrict__ f5,      // (B,  32,  32, C)
    float* __restrict__ out,           // (B, N, 7, 7, C)
    int N, int C, int total)
{
    int idx = blockIdx.x * blockDim.x + threadIdx.x;   // float4 index
    if (idx >= total) return;

    int c4pc = C >> 2;                 // float4 per cell (64)
    int c4   = idx % c4pc;
    int rest = idx / c4pc;
    int cell = rest % CELLS;
    int bn   = rest / CELLS;           // b*N + n
    int b    = bn / N;
    int py   = cell / POOL;
    int px   = cell - py * POOL;

    // ---- box + level selection (warp-uniform) ----
    const float* bx = boxes + (size_t)bn * 4;
    float y1 = bx[0], x1 = bx[1], y2 = bx[2], x2 = bx[3];
    float h = y2 - y1, w = x2 - x1;

    float scale = 224.0f / sqrtf(meta[4] * meta[5]);   // 224/sqrt(image_area)
    float lvl = log2f(sqrtf(h * w) / scale);
    float rl  = 4.0f + rintf(lvl);                     // half-to-even like jnp.round
    rl = fminf(fmaxf(rl, 2.0f), 5.0f);
    int li = (int)rl - 2;                              // 0..3
    int H  = 256 >> li;                                // H == W

    const float* fm = (li == 0) ? f2 : (li == 1) ? f3 : (li == 2) ? f4 : f5;

    // ---- sample coordinates (match reference op order) ----
    float Hm1 = (float)(H - 1);
    float ystep = (h * Hm1) / 6.0f;
    float xstep = (w * Hm1) / 6.0f;
    float ys = y1 * Hm1 + (float)py * ystep;
    float xs = x1 * Hm1 + (float)px * xstep;

    float y0f = floorf(ys), x0f = floorf(xs);
    int y0 = min(max((int)y0f, 0), H - 1);
    int x0 = min(max((int)x0f, 0), H - 1);
    int y1i = min(y0 + 1, H - 1);
    int x1i = min(x0 + 1, H - 1);
    float fy = ys - y0f;
    float fx = xs - x0f;

    // ---- gather 4 corners (coalesced, rows are C-contiguous) ----
    int rowbase = b * H * H;           // b*H*W, fits in int32 (max 33.5M*C? no: element row index)
    const float4* ptl = (const float4*)(fm + (size_t)(rowbase + y0  * H + x0 ) * C) + c4;
    const float4* ptr = (const float4*)(fm + (size_t)(rowbase + y0  * H + x1i) * C) + c4;
    const float4* pbl = (const float4*)(fm + (size_t)(rowbase + y1i * H + x0 ) * C) + c4;
    const float4* pbr = (const float4*)(fm + (size_t)(rowbase + y1i * H + x1i) * C) + c4;

    float4 tl = __ldg(ptl);
    float4 tr = __ldg(ptr);
    float4 bl = __ldg(pbl);
    float4 br = __ldg(pbr);

    float4 r;
    {
        float topx = tl.x + (tr.x - tl.x) * fx;
        float topy = tl.y + (tr.y - tl.y) * fx;
        float topz = tl.z + (tr.z - tl.z) * fx;
        float topw = tl.w + (tr.w - tl.w) * fx;
        float botx = bl.x + (br.x - bl.x) * fx;
        float boty = bl.y + (br.y - bl.y) * fx;
        float botz = bl.z + (br.z - bl.z) * fx;
        float botw = bl.w + (br.w - bl.w) * fx;
        r.x = topx + (botx - topx) * fy;
        r.y = topy + (boty - topy) * fy;
        r.z = topz + (botz - topz) * fy;
        r.w = topw + (botw - topw) * fy;
    }

    ((float4*)out)[idx] = r;
}

extern "C" void kernel_launch(void* const* d_in, const int* in_sizes, int n_in,
                              void* d_out, int out_size) {
    const float* boxes = (const float*)d_in[0];
    const float* meta  = (const float*)d_in[1];
    const float* f2    = (const float*)d_in[2];
    const float* f3    = (const float*)d_in[3];
    const float* f4    = (const float*)d_in[4];
    const float* f5    = (const float*)d_in[5];
    float* out = (float*)d_out;

    int B = in_sizes[1] / 14;                       // image_meta (B,14)
    int N = in_sizes[0] / (4 * B);                  // boxes (B,N,4)
    int C = in_sizes[2] / (B * 256 * 256);          // feat2 (B,256,256,C)

    int total = B * N * CELLS * (C >> 2);           // one float4 per thread
    int threads = 256;
    int blocks = (total + threads - 1) / threads;

    pyramid_roialign_kernel<<<blocks, threads>>>(boxes, meta, f2, f3, f4, f5,
                                                 out, N, C, total);
}

// round 2
// speedup vs baseline: 1.7352x; 1.7352x over previous
#include <cuda_runtime.h>

#define POOL 7
#define CELLS (POOL * POOL)

struct __align__(16) CellParam {
    const float4* tl;
    const float4* tr;
    const float4* bl;
    const float4* br;
    float fx, fy;
    float pad0, pad1;   // pad to 48 bytes (3 x float4)
};

__global__ __launch_bounds__(256) void pyramid_roialign_kernel(
    const float* __restrict__ boxes,   // (B, N, 4)  y1,x1,y2,x2
    const float* __restrict__ meta,    // (B, 14)
    const float* __restrict__ f2,      // (B, 256, 256, C)
    const float* __restrict__ f3,      // (B, 128, 128, C)
    const float* __restrict__ f4,      // (B,  64,  64, C)
    const float* __restrict__ f5,      // (B,  32,  32, C)
    float* __restrict__ out,           // (B, N, 7, 7, C)
    int N, int C)
{
    __shared__ CellParam cp[CELLS];

    const int bn  = blockIdx.x;        // b*N + n
    const int tid = threadIdx.x;

    if (tid < CELLS) {
        const int b = bn / N;
        const float* bx = boxes + (size_t)bn * 4;
        float y1 = bx[0], x1 = bx[1], y2 = bx[2], x2 = bx[3];
        float h = y2 - y1, w = x2 - x1;

        // level selection (identical op order to reference)
        float scale = 224.0f / sqrtf(meta[4] * meta[5]);
        float lvl = log2f(sqrtf(h * w) / scale);
        float rl  = 4.0f + rintf(lvl);           // half-to-even like jnp.round
        rl = fminf(fmaxf(rl, 2.0f), 5.0f);
        int li = (int)rl - 2;                    // 0..3
        int H  = 256 >> li;                      // H == W

        const float* fm = (li == 0) ? f2 : (li == 1) ? f3 : (li == 2) ? f4 : f5;
        const float* base = fm + (size_t)b * H * H * C;

        int py = tid / POOL;
        int px = tid - py * POOL;

        float Hm1 = (float)(H - 1);
        float ys = y1 * Hm1 + (float)py * ((h * Hm1) / 6.0f);
        float xs = x1 * Hm1 + (float)px * ((w * Hm1) / 6.0f);

        float y0f = floorf(ys), x0f = floorf(xs);
        int y0  = min(max((int)y0f, 0), H - 1);
        int x0  = min(max((int)x0f, 0), H - 1);
        int y1i = min(y0 + 1, H - 1);
        int x1i = min(x0 + 1, H - 1);

        CellParam p;
        p.tl = (const float4*)(base + (size_t)(y0  * H + x0 ) * C);
        p.tr = (const float4*)(base + (size_t)(y0  * H + x1i) * C);
        p.bl = (const float4*)(base + (size_t)(y1i * H + x0 ) * C);
        p.br = (const float4*)(base + (size_t)(y1i * H + x1i) * C);
        p.fx = xs - x0f;
        p.fy = ys - y0f;
        p.pad0 = 0.f; p.pad1 = 0.f;
        cp[tid] = p;
    }
    __syncthreads();

    const int c4pc = C >> 2;                 // float4 per cell (64 for C=256)
    const int c4   = tid % c4pc;             // channel-quad
    const int cw   = tid / c4pc;             // starting cell
    const int cstr = blockDim.x / c4pc;      // cell stride (4)

    float4* ob = (float4*)out + (size_t)bn * CELLS * c4pc;

    #pragma unroll 2
    for (int cell = cw; cell < CELLS; cell += cstr) {
        // warp-uniform smem reads (broadcast)
        const float4* ptl = cp[cell].tl + c4;
        const float4* ptr = cp[cell].tr + c4;
        const float4* pbl = cp[cell].bl + c4;
        const float4* pbr = cp[cell].br + c4;
        float fx = cp[cell].fx;
        float fy = cp[cell].fy;

        float4 tl = __ldg(ptl);
        float4 tr = __ldg(ptr);
        float4 bl = __ldg(pbl);
        float4 br = __ldg(pbr);

        float4 r;
        float topx = tl.x + (tr.x - tl.x) * fx;
        float topy = tl.y + (tr.y - tl.y) * fx;
        float topz = tl.z + (tr.z - tl.z) * fx;
        float topw = tl.w + (tr.w - tl.w) * fx;
        float botx = bl.x + (br.x - bl.x) * fx;
        float boty = bl.y + (br.y - bl.y) * fx;
        float botz = bl.z + (br.z - bl.z) * fx;
        float botw = bl.w + (br.w - bl.w) * fx;
        r.x = topx + (botx - topx) * fy;
        r.y = topy + (boty - topy) * fy;
        r.z = topz + (botz - topz) * fy;
        r.w = topw + (botw - topw) * fy;

        ob[cell * c4pc + c4] = r;
    }
}

extern "C" void kernel_launch(void* const* d_in, const int* in_sizes, int n_in,
                              void* d_out, int out_size) {
    const float* boxes = (const float*)d_in[0];
    const float* meta  = (const float*)d_in[1];
    const float* f2    = (const float*)d_in[2];
    const float* f3    = (const float*)d_in[3];
    const float* f4    = (const float*)d_in[4];
    const float* f5    = (const float*)d_in[5];
    float* out = (float*)d_out;

    int B = in_sizes[1] / 14;                       // image_meta (B,14)
    int N = in_sizes[0] / (4 * B);                  // boxes (B,N,4)
    int C = in_sizes[2] / (B * 256 * 256);          // feat2 (B,256,256,C)

    int blocks = B * N;                             // one block per box
    pyramid_roialign_kernel<<<blocks, 256>>>(boxes, meta, f2, f3, f4, f5,
                                             out, N, C);
}

// round 3
// speedup vs baseline: 1.7597x; 1.0141x over previous
#include <cuda_runtime.h>

#define POOL 7
#define CELLS (POOL * POOL)

// ---------------- optimized path: C == 256 (c4pc = 64) ----------------
// One block per box, 256 threads = 8 warps. Warp w handles cells w, w+8, ...
// Each lane handles channel-quads (lane) and (lane+32) of the cell:
// 8 independent LDG.128 per iteration (MLP=8), fully coalesced 512B bursts.

__global__ __launch_bounds__(256) void roialign_c256_kernel(
    const float* __restrict__ boxes,
    const float* __restrict__ meta,
    const float* __restrict__ f2,
    const float* __restrict__ f3,
    const float* __restrict__ f4,
    const float* __restrict__ f5,
    float* __restrict__ out,
    int N)
{
    __shared__ int4   s_off[CELLS];          // quad offsets: tl,tr,bl,br
    __shared__ float2 s_f[CELLS];            // fx, fy
    __shared__ const float4* s_base;         // block-uniform level base

    const int bn  = blockIdx.x;
    const int tid = threadIdx.x;
    const int C   = 256;

    if (tid < CELLS) {
        const int b = bn / N;
        const float* bx = boxes + (size_t)bn * 4;
        float y1 = bx[0], x1 = bx[1], y2 = bx[2], x2 = bx[3];
        float h = y2 - y1, w = x2 - x1;

        float scale = 224.0f / sqrtf(meta[4] * meta[5]);
        float lvl = log2f(sqrtf(h * w) / scale);
        float rl  = 4.0f + rintf(lvl);                 // half-to-even
        rl = fminf(fmaxf(rl, 2.0f), 5.0f);
        int li = (int)rl - 2;
        int H  = 256 >> li;

        const float* fm = (li == 0) ? f2 : (li == 1) ? f3 : (li == 2) ? f4 : f5;
        const float* base = fm + (size_t)b * H * H * C;

        int py = tid / POOL;
        int px = tid - py * POOL;

        float Hm1 = (float)(H - 1);
        float ys = y1 * Hm1 + (float)py * ((h * Hm1) / 6.0f);
        float xs = x1 * Hm1 + (float)px * ((w * Hm1) / 6.0f);

        float y0f = floorf(ys), x0f = floorf(xs);
        int y0  = min(max((int)y0f, 0), H - 1);
        int x0  = min(max((int)x0f, 0), H - 1);
        int y1i = min(y0 + 1, H - 1);
        int x1i = min(x0 + 1, H - 1);

        int c4 = C >> 2;   // 64 quads per row
        int4 off;
        off.x = (y0  * H + x0 ) * c4;
        off.y = (y0  * H + x1i) * c4;
        off.z = (y1i * H + x0 ) * c4;
        off.w = (y1i * H + x1i) * c4;
        s_off[tid] = off;
        s_f[tid] = make_float2(xs - x0f, ys - y0f);
        if (tid == 0) s_base = (const float4*)base;
    }
    __syncthreads();

    const float4* base = s_base;             // register, block-uniform
    const int warp = tid >> 5;
    const int lane = tid & 31;

    float4* ob = (float4*)out + (size_t)bn * CELLS * 64;

    for (int cell = warp; cell < CELLS; cell += 8) {
        int4   off = s_off[cell];
        float2 f   = s_f[cell];
        float fx = f.x, fy = f.y;

        // 8 independent coalesced loads (front-batched MLP=8)
        float4 tl0 = __ldg(base + off.x + lane);
        float4 tr0 = __ldg(base + off.y + lane);
        float4 bl0 = __ldg(base + off.z + lane);
        float4 br0 = __ldg(base + off.w + lane);
        float4 tl1 = __ldg(base + off.x + lane + 32);
        float4 tr1 = __ldg(base + off.y + lane + 32);
        float4 bl1 = __ldg(base + off.z + lane + 32);
        float4 br1 = __ldg(base + off.w + lane + 32);

        float4 r0, r1;
        {
            float tx = tl0.x + (tr0.x - tl0.x) * fx;
            float ty = tl0.y + (tr0.y - tl0.y) * fx;
            float tz = tl0.z + (tr0.z - tl0.z) * fx;
            float tw = tl0.w + (tr0.w - tl0.w) * fx;
            float bxx = bl0.x + (br0.x - bl0.x) * fx;
            float bxy = bl0.y + (br0.y - bl0.y) * fx;
            float bxz = bl0.z + (br0.z - bl0.z) * fx;
            float bxw = bl0.w + (br0.w - bl0.w) * fx;
            r0.x = tx + (bxx - tx) * fy;
            r0.y = ty + (bxy - ty) * fy;
            r0.z = tz + (bxz - tz) * fy;
            r0.w = tw + (bxw - tw) * fy;
        }
        {
            float tx = tl1.x + (tr1.x - tl1.x) * fx;
            float ty = tl1.y + (tr1.y - tl1.y) * fx;
            float tz = tl1.z + (tr1.z - tl1.z) * fx;
            float tw = tl1.w + (tr1.w - tl1.w) * fx;
            float bxx = bl1.x + (br1.x - bl1.x) * fx;
            float bxy = bl1.y + (br1.y - bl1.y) * fx;
            float bxz = bl1.z + (br1.z - bl1.z) * fx;
            float bxw = bl1.w + (br1.w - bl1.w) * fx;
            r1.x = tx + (bxx - tx) * fy;
            r1.y = ty + (bxy - ty) * fy;
            r1.z = tz + (bxz - tz) * fy;
            r1.w = tw + (bxw - tw) * fy;
        }

        __stcs(ob + cell * 64 + lane,      r0);
        __stcs(ob + cell * 64 + lane + 32, r1);
    }
}

// ---------------- generic fallback (any C divisible by 4) ----------------

struct __align__(16) CellParam {
    const float4* tl;
    const float4* tr;
    const float4* bl;
    const float4* br;
    float fx, fy;
    float pad0, pad1;
};

__global__ __launch_bounds__(256) void roialign_generic_kernel(
    const float* __restrict__ boxes,
    const float* __restrict__ meta,
    const float* __restrict__ f2,
    const float* __restrict__ f3,
    const float* __restrict__ f4,
    const float* __restrict__ f5,
    float* __restrict__ out,
    int N, int C)
{
    __shared__ CellParam cp[CELLS];
    const int bn  = blockIdx.x;
    const int tid = threadIdx.x;

    if (tid < CELLS) {
        const int b = bn / N;
        const float* bx = boxes + (size_t)bn * 4;
        float y1 = bx[0], x1 = bx[1], y2 = bx[2], x2 = bx[3];
        float h = y2 - y1, w = x2 - x1;
        float scale = 224.0f / sqrtf(meta[4] * meta[5]);
        float lvl = log2f(sqrtf(h * w) / scale);
        float rl  = 4.0f + rintf(lvl);
        rl = fminf(fmaxf(rl, 2.0f), 5.0f);
        int li = (int)rl - 2;
        int H  = 256 >> li;
        const float* fm = (li == 0) ? f2 : (li == 1) ? f3 : (li == 2) ? f4 : f5;
        const float* base = fm + (size_t)b * H * H * C;
        int py = tid / POOL;
        int px = tid - py * POOL;
        float Hm1 = (float)(H - 1);
        float ys = y1 * Hm1 + (float)py * ((h * Hm1) / 6.0f);
        float xs = x1 * Hm1 + (float)px * ((w * Hm1) / 6.0f);
        float y0f = floorf(ys), x0f = floorf(xs);
        int y0  = min(max((int)y0f, 0), H - 1);
        int x0  = min(max((int)x0f, 0), H - 1);
        int y1i = min(y0 + 1, H - 1);
        int x1i = min(x0 + 1, H - 1);
        CellParam p;
        p.tl = (const float4*)(base + (size_t)(y0  * H + x0 ) * C);
        p.tr = (const float4*)(base + (size_t)(y0  * H + x1i) * C);
        p.bl = (const float4*)(base + (size_t)(y1i * H + x0 ) * C);
        p.br = (const float4*)(base + (size_t)(y1i * H + x1i) * C);
        p.fx = xs - x0f;
        p.fy = ys - y0f;
        p.pad0 = 0.f; p.pad1 = 0.f;
        cp[tid] = p;
    }
    __syncthreads();

    const int c4pc = C >> 2;
    const int c4   = tid % c4pc;
    const int cw   = tid / c4pc;
    const int cstr = blockDim.x / c4pc;
    float4* ob = (float4*)out + (size_t)bn * CELLS * c4pc;

    for (int cell = cw; cell < CELLS; cell += cstr) {
        float fx = cp[cell].fx, fy = cp[cell].fy;
        float4 tl = __ldg(cp[cell].tl + c4);
        float4 tr = __ldg(cp[cell].tr + c4);
        float4 bl = __ldg(cp[cell].bl + c4);
        float4 br = __ldg(cp[cell].br + c4);
        float4 r;
        float tx = tl.x + (tr.x - tl.x) * fx;
        float ty = tl.y + (tr.y - tl.y) * fx;
        float tz = tl.z + (tr.z - tl.z) * fx;
        float tw = tl.w + (tr.w - tl.w) * fx;
        float bxx = bl.x + (br.x - bl.x) * fx;
        float bxy = bl.y + (br.y - bl.y) * fx;
        float bxz = bl.z + (br.z - bl.z) * fx;
        float bxw = bl.w + (br.w - bl.w) * fx;
        r.x = tx + (bxx - tx) * fy;
        r.y = ty + (bxy - ty) * fy;
        r.z = tz + (bxz - tz) * fy;
        r.w = tw + (bxw - tw) * fy;
        ob[cell * c4pc + c4] = r;
    }
}

extern "C" void kernel_launch(void* const* d_in, const int* in_sizes, int n_in,
                              void* d_out, int out_size) {
    const float* boxes = (const float*)d_in[0];
    const float* meta  = (const float*)d_in[1];
    const float* f2    = (const float*)d_in[2];
    const float* f3    = (const float*)d_in[3];
    const float* f4    = (const float*)d_in[4];
    const float* f5    = (const float*)d_in[5];
    float* out = (float*)d_out;

    int B = in_sizes[1] / 14;
    int N = in_sizes[0] / (4 * B);
    int C = in_sizes[2] / (B * 256 * 256);

    int blocks = B * N;
    if (C == 256) {
        roialign_c256_kernel<<<blocks, 256>>>(boxes, meta, f2, f3, f4, f5, out, N);
    } else {
        roialign_generic_kernel<<<blocks, 256>>>(boxes, meta, f2, f3, f4, f5, out, N, C);
    }
}